// round 3
// baseline (speedup 1.0000x reference)
#include <cuda_runtime.h>

// Problem constants (shapes fixed by the dataset)
#define BB   64
#define KK   8
#define VV   128000
#define NS   25            // chunks per batch row
#define TPB  256
#define LCH  (VV / NS)     // 5120 elements per chunk
#define PER_T (LCH / TPB)  // 20 elements per thread (5 x float4)

// Scratch (device globals — no allocation allowed)
__device__ float g_tsum[(long)BB * NS * TPB];  // per-thread partial sums (pass 1)
__device__ float g_chunksum[BB * NS];
__device__ int   g_r[BB];
__device__ int   g_allacc[BB];
__device__ int   g_na[BB];
__device__ int   g_count[BB];
__device__ int   g_done[BB];

// ---------------------------------------------------------------------------
// Kernel A: acceptance chain per batch + token scaffolding + state init
// Output written as FLOAT32 (harness output dtype; -1 as int bits is NaN-in-
// float, which was the source of the previous rel_err=nan failures).
// ---------------------------------------------------------------------------
__global__ void k_accept(const int* __restrict__ dtok,
                         const float* __restrict__ dp,
                         const float* __restrict__ op,
                         const float* __restrict__ unif,
                         float* __restrict__ out)
{
    int b = threadIdx.x;
    if (b >= BB) return;

    int na = 0;
    bool acc = true;
#pragma unroll
    for (int k = 0; k < KK; ++k) {
        int tok  = dtok[b * KK + k];
        tok = max(0, min(tok, VV - 1));   // defensive clamp
        float pd = dp[((long)b * KK + k) * VV + tok];
        float po = op[((long)b * (KK + 1) + k) * VV + tok];
        float ap = fminf(1.0f, po / pd);
        bool a = acc && (unif[b * KK + k] < ap);
        if (a) na++; else acc = false;
    }
    g_r[b]      = min(na, KK - 1);
    g_allacc[b] = (na == KK) ? 1 : 0;
    g_na[b]     = na;
    g_count[b]  = 0;
    g_done[b]   = 0;

#pragma unroll
    for (int pos = 0; pos <= KK; ++pos) {
        float tv;
        if (pos < na)       tv = (float)dtok[b * KK + pos];
        else if (pos == na) tv = 0.0f;   // placeholder; overwritten by last count block
        else                tv = -1.0f;
        out[b * (KK + 1) + pos] = tv;
    }
    out[BB * (KK + 1) + b] = (float)na;  // num_accepted block of output
}

// Shared value loader: residual max(o-d,0) or bonus row, 20 contiguous floats.
__device__ __forceinline__ void load_vals(const float* __restrict__ dp,
                                          const float* __restrict__ op,
                                          int b, int s, int t,
                                          int allacc, int r,
                                          float vals[PER_T])
{
    long off   = (long)s * LCH + (long)t * PER_T;
    long obase = ((long)b * (KK + 1) + (allacc ? KK : r)) * VV + off;
    const float4* o4 = (const float4*)(op + obase);
    if (allacc) {
#pragma unroll
        for (int i = 0; i < PER_T / 4; ++i) {
            float4 o = o4[i];
            vals[4*i+0] = o.x; vals[4*i+1] = o.y;
            vals[4*i+2] = o.z; vals[4*i+3] = o.w;
        }
    } else {
        long dbase = ((long)b * KK + r) * VV + off;
        const float4* d4 = (const float4*)(dp + dbase);
#pragma unroll
        for (int i = 0; i < PER_T / 4; ++i) {
            float4 o = o4[i];
            float4 d = d4[i];
            vals[4*i+0] = fmaxf(o.x - d.x, 0.0f);
            vals[4*i+1] = fmaxf(o.y - d.y, 0.0f);
            vals[4*i+2] = fmaxf(o.z - d.z, 0.0f);
            vals[4*i+3] = fmaxf(o.w - d.w, 0.0f);
        }
    }
}

// ---------------------------------------------------------------------------
// Kernel B (pass 1): per-thread + per-chunk partial sums of the residual
// ---------------------------------------------------------------------------
__global__ void k_partial(const float* __restrict__ dp,
                          const float* __restrict__ op)
{
    int blk = blockIdx.x;
    int b = blk / NS, s = blk % NS;
    int t = threadIdx.x;

    float vals[PER_T];
    load_vals(dp, op, b, s, t, g_allacc[b], g_r[b], vals);

    float sum = 0.0f;
#pragma unroll
    for (int i = 0; i < PER_T; ++i) sum += vals[i];

    g_tsum[(long)blk * TPB + t] = sum;

    // block reduce -> chunk sum
    float w = sum;
#pragma unroll
    for (int off = 16; off > 0; off >>= 1)
        w += __shfl_down_sync(0xFFFFFFFFu, w, off);
    __shared__ float sred[TPB / 32];
    if ((t & 31) == 0) sred[t >> 5] = w;
    __syncthreads();
    if (t < TPB / 32) {
        float x = sred[t];
#pragma unroll
        for (int off = 4; off > 0; off >>= 1)
            x += __shfl_down_sync(0xFFu, x, off);
        if (t == 0) g_chunksum[blk] = x;
    }
}

// ---------------------------------------------------------------------------
// Kernel C (pass 2): count positions with inclusive prefix < T; last block
// per batch writes the sampled token into the output (as float).
// ---------------------------------------------------------------------------
__global__ void k_count(const float* __restrict__ dp,
                        const float* __restrict__ op,
                        const float* __restrict__ su,
                        float* __restrict__ out)
{
    int blk = blockIdx.x;
    int b = blk / NS, s = blk % NS;
    int t = threadIdx.x;
    int lane = t & 31, wid = t >> 5;

    int allacc = g_allacc[b];
    int r      = g_r[b];

    // exclusive chunk base + total (25 cached reads, redundant per block: cheap)
    float cbase = 0.0f, tot = 0.0f;
#pragma unroll
    for (int j = 0; j < NS; ++j) {
        float cs = g_chunksum[b * NS + j];
        if (j < s) cbase += cs;
        tot += cs;
    }
    float T = allacc ? su[b] : su[b] * tot;

    float my = g_tsum[(long)blk * TPB + t];

    // block-wide inclusive scan of per-thread sums (warp shuffle scan)
    float x = my;
#pragma unroll
    for (int off = 1; off < 32; off <<= 1) {
        float y = __shfl_up_sync(0xFFFFFFFFu, x, off);
        if (lane >= off) x += y;
    }
    __shared__ float wtot[TPB / 32];
    if (lane == 31) wtot[wid] = x;
    __syncthreads();
    if (wid == 0 && lane < TPB / 32) {
        float w = wtot[lane];
#pragma unroll
        for (int off = 1; off < TPB / 32; off <<= 1) {
            float y = __shfl_up_sync(0xFFu, w, off);
            if (lane >= off) w += y;
        }
        wtot[lane] = w;
    }
    __syncthreads();

    float base = cbase + (x - my) + (wid > 0 ? wtot[wid - 1] : 0.0f);

    float vals[PER_T];
    load_vals(dp, op, b, s, t, allacc, r, vals);

    int cnt = 0;
    float run = base;
#pragma unroll
    for (int i = 0; i < PER_T; ++i) {
        run += vals[i];
        cnt += (run < T) ? 1 : 0;
    }

    // reduce count across block, single atomic per block
#pragma unroll
    for (int off = 16; off > 0; off >>= 1)
        cnt += __shfl_down_sync(0xFFFFFFFFu, cnt, off);
    __shared__ int cred[TPB / 32];
    if (lane == 0) cred[wid] = cnt;
    __syncthreads();
    if (t == 0) {
        int c = 0;
#pragma unroll
        for (int j = 0; j < TPB / 32; ++j) c += cred[j];
        atomicAdd(&g_count[b], c);
        __threadfence();
        int old = atomicAdd(&g_done[b], 1);
        if (old == NS - 1) {
            // last block for this batch: all count contributions visible
            int total = atomicAdd(&g_count[b], 0);
            int nt = min(total, VV - 1);
            out[b * (KK + 1) + g_na[b]] = (float)nt;
        }
    }
}

// ---------------------------------------------------------------------------
// Host launcher: classify inputs by element count (order-agnostic).
// ---------------------------------------------------------------------------
extern "C" void kernel_launch(void* const* d_in, const int* in_sizes, int n_in,
                              void* d_out, int out_size)
{
    const int*   dtok = nullptr;
    const float* dp   = nullptr;
    const float* op   = nullptr;
    const float* unif = nullptr;
    const float* su   = nullptr;

    int n512 = 0;
    for (int i = 0; i < n_in; ++i) {
        long sz = (long)in_sizes[i];
        if (sz == (long)BB * KK * VV)            dp = (const float*)d_in[i];
        else if (sz == (long)BB * (KK + 1) * VV) op = (const float*)d_in[i];
        else if (sz == BB)                       su = (const float*)d_in[i];
        else if (sz == BB * KK) {
            // relative order under both insertion and alphabetical metadata
            // ordering: draft_tokens, oracle_tokens, uniforms
            if      (n512 == 0) dtok = (const int*)d_in[i];
            else if (n512 == 2) unif = (const float*)d_in[i];
            ++n512;
        }
        // size-1 scalar (num_draft_tokens) ignored: compile-time KK
    }

    float* out = (float*)d_out;  // [tokens (B*(K+1)) | num_accepted (B)] as f32

    k_accept <<<1, BB>>>(dtok, dp, op, unif, out);
    k_partial<<<BB * NS, TPB>>>(dp, op);
    k_count  <<<BB * NS, TPB>>>(dp, op, su, out);
}

// round 4
// speedup vs baseline: 1.4863x; 1.4863x over previous
#include <cuda_runtime.h>

// Problem constants (shapes fixed by the dataset)
#define BB   64
#define KK   8
#define VV   128000
#define NS   25            // chunks per batch row
#define TPB  256
#define LCH  (VV / NS)     // 5120 elements per chunk
#define PER_T (LCH / TPB)  // 20 elements per thread (5 x float4)
#define FULL 0xFFFFFFFFu

// Scratch (device globals — no allocation allowed)
__device__ float g_tsum[(long)BB * NS * TPB];  // per-thread partial sums (pass 1)
__device__ float g_chunksum[BB * NS];
__device__ int   g_r[BB];
__device__ int   g_allacc[BB];
__device__ int   g_na[BB];

// ---------------------------------------------------------------------------
// Kernel A: acceptance chain, one warp per batch (parallel gathers).
// Output is FLOAT32 (harness output dtype).
// ---------------------------------------------------------------------------
__global__ void k_accept(const int* __restrict__ dtok,
                         const float* __restrict__ dp,
                         const float* __restrict__ op,
                         const float* __restrict__ unif,
                         float* __restrict__ out)
{
    int b    = blockIdx.x;
    int lane = threadIdx.x;

    bool acc = false;
    if (lane < KK) {
        int tok  = dtok[b * KK + lane];
        float pd = dp[((long)b * KK + lane) * VV + tok];
        float po = op[((long)b * (KK + 1) + lane) * VV + tok];
        acc = unif[b * KK + lane] < fminf(1.0f, po / pd);
    }
    unsigned bits = __ballot_sync(FULL, acc) & ((1u << KK) - 1u);
    int na = __ffs(~bits) - 1;          // first rejected position; 8 if all accepted

    if (lane == 0) {
        g_r[b]      = min(na, KK - 1);
        g_allacc[b] = (na == KK) ? 1 : 0;
        g_na[b]     = na;
        out[BB * (KK + 1) + b] = (float)na;   // num_accepted block
    }
    if (lane <= KK) {
        float tv;
        if (lane < na)       tv = (float)dtok[b * KK + lane];
        else if (lane == na) tv = 0.0f;       // placeholder; k_search overwrites
        else                 tv = -1.0f;
        out[b * (KK + 1) + lane] = tv;
    }
}

// Shared value loader: residual max(o-d,0) or bonus row, 20 contiguous floats.
__device__ __forceinline__ void load_vals(const float* __restrict__ dp,
                                          const float* __restrict__ op,
                                          int b, int s, int t,
                                          int allacc, int r,
                                          float vals[PER_T])
{
    long off   = (long)s * LCH + (long)t * PER_T;
    long obase = ((long)b * (KK + 1) + (allacc ? KK : r)) * VV + off;
    const float4* o4 = (const float4*)(op + obase);
    if (allacc) {
#pragma unroll
        for (int i = 0; i < PER_T / 4; ++i) {
            float4 o = o4[i];
            vals[4*i+0] = o.x; vals[4*i+1] = o.y;
            vals[4*i+2] = o.z; vals[4*i+3] = o.w;
        }
    } else {
        long dbase = ((long)b * KK + r) * VV + off;
        const float4* d4 = (const float4*)(dp + dbase);
#pragma unroll
        for (int i = 0; i < PER_T / 4; ++i) {
            float4 o = o4[i];
            float4 d = d4[i];
            vals[4*i+0] = fmaxf(o.x - d.x, 0.0f);
            vals[4*i+1] = fmaxf(o.y - d.y, 0.0f);
            vals[4*i+2] = fmaxf(o.z - d.z, 0.0f);
            vals[4*i+3] = fmaxf(o.w - d.w, 0.0f);
        }
    }
}

// ---------------------------------------------------------------------------
// Kernel B (single streaming pass): per-thread sums + per-chunk sums.
// ---------------------------------------------------------------------------
__global__ void k_partial(const float* __restrict__ dp,
                          const float* __restrict__ op)
{
    int blk = blockIdx.x;
    int b = blk / NS, s = blk % NS;
    int t = threadIdx.x;

    float vals[PER_T];
    load_vals(dp, op, b, s, t, g_allacc[b], g_r[b], vals);

    float sum = 0.0f;
#pragma unroll
    for (int i = 0; i < PER_T; ++i) sum += vals[i];   // sequential order (matters!)

    g_tsum[(long)blk * TPB + t] = sum;

    // block reduce -> chunk sum
    float w = sum;
#pragma unroll
    for (int off = 16; off > 0; off >>= 1)
        w += __shfl_down_sync(FULL, w, off);
    __shared__ float sred[TPB / 32];
    if ((t & 31) == 0) sred[t >> 5] = w;
    __syncthreads();
    if (t < TPB / 32) {
        float x = sred[t];
#pragma unroll
        for (int off = 4; off > 0; off >>= 1)
            x += __shfl_down_sync(0xFFu, x, off);
        if (t == 0) g_chunksum[blk] = x;
    }
}

// ---------------------------------------------------------------------------
// Kernel C: hierarchical CDF search, one warp per batch.
// Monotone CDF (values >= 0) => count(cdf < T) = first crossing index.
// ---------------------------------------------------------------------------
__global__ void k_search(const float* __restrict__ dp,
                         const float* __restrict__ op,
                         const float* __restrict__ su,
                         float* __restrict__ out)
{
    int b    = blockIdx.x;
    int lane = threadIdx.x;

    int allacc = g_allacc[b];
    int r      = g_r[b];
    int na     = g_na[b];

    // ---- level 1: chunk sums (25 values) ----
    float cs = (lane < NS) ? g_chunksum[b * NS + lane] : 0.0f;
    float x = cs;
#pragma unroll
    for (int off = 1; off < 32; off <<= 1) {
        float y = __shfl_up_sync(FULL, x, off);
        if (lane >= off) x += y;
    }
    float tot = __shfl_sync(FULL, x, NS - 1);
    float T = allacc ? su[b] : su[b] * tot;

    unsigned bal = __ballot_sync(FULL, (lane < NS) && (x >= T));
    int token;
    if (bal == 0) {
        token = VV - 1;                         // u beyond total mass
    } else {
        int s = __ffs(bal) - 1;                 // chunk containing the crossing
        float base = __shfl_sync(FULL, x, s) - __shfl_sync(FULL, cs, s);

        // ---- level 2: 256 thread sums in chunk s, scanned 32 at a time ----
        const float* ts = &g_tsum[(long)(b * NS + s) * TPB];
        int   t_found = -1;
        float base_t  = 0.0f;
        float running = base;
#pragma unroll
        for (int g = 0; g < TPB / 32; ++g) {
            float v = ts[g * 32 + lane];
            float xx = v;
#pragma unroll
            for (int off = 1; off < 32; off <<= 1) {
                float y = __shfl_up_sync(FULL, xx, off);
                if (lane >= off) xx += y;
            }
            unsigned bb2 = __ballot_sync(FULL, running + xx >= T);
            if (bb2) {
                int l = __ffs(bb2) - 1;
                t_found = g * 32 + l;
                base_t  = running + __shfl_sync(FULL, xx, l)
                                  - __shfl_sync(FULL, v, l);
                break;
            }
            running += __shfl_sync(FULL, xx, 31);
        }

        if (t_found < 0) {
            token = min(s * LCH + LCH, VV - 1); // ulp-tie fallback
        } else {
            // ---- level 3: 20 elements of thread t_found, sequential on lane 0 ----
            long off0  = (long)s * LCH + (long)t_found * PER_T;
            long obase = ((long)b * (KK + 1) + (allacc ? KK : r)) * VV + off0;
            long dbase = ((long)b * KK + r) * VV + off0;
            float val = 0.0f;
            if (lane < PER_T) {
                float o = op[obase + lane];
                val = allacc ? o : fmaxf(o - dp[dbase + lane], 0.0f);
            }
            int idx = PER_T;                    // fallback: end of this thread's span
            if (lane == 0) {
                float run = base_t;
                for (int i = 0; i < PER_T; ++i) {
                    run += __shfl_sync(1u, val, 0);  // placeholder, replaced below
                }
            }
            // gather the 20 values serially via shuffles (all lanes participate)
            float run = base_t;
            int found = PER_T;
#pragma unroll
            for (int i = 0; i < PER_T; ++i) {
                float v = __shfl_sync(FULL, val, i);
                run += v;
                if (found == PER_T && run >= T) found = i;
            }
            idx = found;
            token = min((int)(off0 + idx), VV - 1);
        }
    }

    if (lane == 0)
        out[b * (KK + 1) + na] = (float)token;
}

// ---------------------------------------------------------------------------
// Host launcher: classify inputs by element count (order-agnostic).
// ---------------------------------------------------------------------------
extern "C" void kernel_launch(void* const* d_in, const int* in_sizes, int n_in,
                              void* d_out, int out_size)
{
    const int*   dtok = nullptr;
    const float* dp   = nullptr;
    const float* op   = nullptr;
    const float* unif = nullptr;
    const float* su   = nullptr;

    int n512 = 0;
    for (int i = 0; i < n_in; ++i) {
        long sz = (long)in_sizes[i];
        if (sz == (long)BB * KK * VV)            dp = (const float*)d_in[i];
        else if (sz == (long)BB * (KK + 1) * VV) op = (const float*)d_in[i];
        else if (sz == BB)                       su = (const float*)d_in[i];
        else if (sz == BB * KK) {
            // relative order: draft_tokens, oracle_tokens, uniforms
            if      (n512 == 0) dtok = (const int*)d_in[i];
            else if (n512 == 2) unif = (const float*)d_in[i];
            ++n512;
        }
    }

    float* out = (float*)d_out;  // [tokens (B*(K+1)) | num_accepted (B)] as f32

    k_accept <<<BB, 32>>>(dtok, dp, op, unif, out);
    k_partial<<<BB * NS, TPB>>>(dp, op);
    k_search <<<BB, 32>>>(dp, op, su, out);
}

// round 5
// speedup vs baseline: 1.5234x; 1.0250x over previous
#include <cuda_runtime.h>

// Problem constants (shapes fixed by the dataset)
#define BB   64
#define KK   8
#define VV   128000
#define NS   25            // chunks per batch row
#define TPB  256
#define LCH  (VV / NS)     // 5120 elements per chunk
#define PER_T (LCH / TPB)  // 20 elements per thread (5 x float4)
#define FULL 0xFFFFFFFFu

// Scratch (device globals — zero-initialized; g_done self-resets every call)
__device__ float g_tsum[(long)BB * NS * TPB];
__device__ float g_chunksum[BB * NS];
__device__ int   g_done[BB];

// Residual max(o-d,0) or bonus row: 20 contiguous floats for (b, s, t).
__device__ __forceinline__ void load_vals(const float* __restrict__ dp,
                                          const float* __restrict__ op,
                                          int b, int s, int t,
                                          int allacc, int r,
                                          float vals[PER_T])
{
    long off   = (long)s * LCH + (long)t * PER_T;
    long obase = ((long)b * (KK + 1) + (allacc ? KK : r)) * VV + off;
    const float4* o4 = (const float4*)(op + obase);
    if (allacc) {
#pragma unroll
        for (int i = 0; i < PER_T / 4; ++i) {
            float4 o = o4[i];
            vals[4*i+0] = o.x; vals[4*i+1] = o.y;
            vals[4*i+2] = o.z; vals[4*i+3] = o.w;
        }
    } else {
        long dbase = ((long)b * KK + r) * VV + off;
        const float4* d4 = (const float4*)(dp + dbase);
#pragma unroll
        for (int i = 0; i < PER_T / 4; ++i) {
            float4 o = o4[i];
            float4 d = d4[i];
            vals[4*i+0] = fmaxf(o.x - d.x, 0.0f);
            vals[4*i+1] = fmaxf(o.y - d.y, 0.0f);
            vals[4*i+2] = fmaxf(o.z - d.z, 0.0f);
            vals[4*i+3] = fmaxf(o.w - d.w, 0.0f);
        }
    }
}

// ---------------------------------------------------------------------------
// Single fused kernel: acceptance (redundant per block, L2-hot) + streaming
// partial sums + last-block hierarchical CDF search.
// ---------------------------------------------------------------------------
__global__ void __launch_bounds__(TPB)
k_fused(const int*   __restrict__ dtok,
        const float* __restrict__ dp,
        const float* __restrict__ op,
        const float* __restrict__ unif,
        const float* __restrict__ su,
        float*       __restrict__ out)
{
    int blk = blockIdx.x;
    int b = blk / NS, s = blk % NS;
    int t = threadIdx.x;
    int lane = t & 31, wid = t >> 5;

    // ---- acceptance (warp 0), broadcast via shared ----
    __shared__ int sh_na;
    if (wid == 0) {
        bool acc = false;
        if (lane < KK) {
            int tok  = dtok[b * KK + lane];
            float pd = dp[((long)b * KK + lane) * VV + tok];
            float po = op[((long)b * (KK + 1) + lane) * VV + tok];
            acc = unif[b * KK + lane] < fminf(1.0f, po / pd);
        }
        unsigned bits = __ballot_sync(FULL, acc) & ((1u << KK) - 1u);
        if (lane == 0) sh_na = __ffs(~bits) - 1;   // 8 if all accepted
    }
    __syncthreads();
    int na     = sh_na;
    int allacc = (na == KK) ? 1 : 0;
    int r      = min(na, KK - 1);

    // ---- token scaffolding: block s==0 writes every slot except position na ----
    if (s == 0) {
        if (t <= KK && t != na)
            out[b * (KK + 1) + t] = (t < na) ? (float)dtok[b * KK + t] : -1.0f;
        if (t == 0)
            out[BB * (KK + 1) + b] = (float)na;    // num_accepted block
    }

    // ---- streaming pass: per-thread sum (sequential order!) + chunk sum ----
    float vals[PER_T];
    load_vals(dp, op, b, s, t, allacc, r, vals);
    float sum = 0.0f;
#pragma unroll
    for (int i = 0; i < PER_T; ++i) sum += vals[i];
    g_tsum[(long)blk * TPB + t] = sum;

    float w = sum;
#pragma unroll
    for (int off = 16; off > 0; off >>= 1)
        w += __shfl_down_sync(FULL, w, off);
    __shared__ float sred[TPB / 32];
    if (lane == 0) sred[wid] = w;
    __syncthreads();
    if (t == 0) {
        float x = 0.0f;
#pragma unroll
        for (int j = 0; j < TPB / 32; ++j) x += sred[j];
        g_chunksum[blk] = x;
    }

    // ---- publish + elect last block of this batch ----
    __shared__ int sh_last;
    __syncthreads();                 // all g_tsum/g_chunksum writes issued
    if (t == 0) {
        __threadfence();             // make them device-visible
        int old = atomicAdd(&g_done[b], 1);
        sh_last = (old == NS - 1);
    }
    __syncthreads();
    if (!sh_last) return;
    if (t == 0) g_done[b] = 0;       // self-reset for next call / graph replay
    if (wid != 0) return;

    __threadfence();                 // acquire side before cross-block reads

    // ---- hierarchical CDF search (warp 0 of last block) ----
    // level 1: 25 chunk sums
    float cs = (lane < NS) ? __ldcg(&g_chunksum[b * NS + lane]) : 0.0f;
    float x = cs;
#pragma unroll
    for (int off = 1; off < 32; off <<= 1) {
        float y = __shfl_up_sync(FULL, x, off);
        if (lane >= off) x += y;
    }
    float tot = __shfl_sync(FULL, x, NS - 1);
    float T = allacc ? su[b] : su[b] * tot;

    unsigned bal = __ballot_sync(FULL, (lane < NS) && (x >= T));
    int token;
    if (bal == 0) {
        token = VV - 1;                              // u beyond total mass
    } else {
        int sc = __ffs(bal) - 1;                     // chunk with the crossing
        float base = __shfl_sync(FULL, x, sc) - __shfl_sync(FULL, cs, sc);

        // level 2: 256 thread sums in chunk sc, 32 at a time
        const float* ts = &g_tsum[(long)(b * NS + sc) * TPB];
        int   t_found = -1;
        float base_t  = 0.0f;
        float running = base;
#pragma unroll
        for (int g = 0; g < TPB / 32; ++g) {
            float v = __ldcg(&ts[g * 32 + lane]);
            float xx = v;
#pragma unroll
            for (int off = 1; off < 32; off <<= 1) {
                float y = __shfl_up_sync(FULL, xx, off);
                if (lane >= off) xx += y;
            }
            unsigned bb2 = __ballot_sync(FULL, running + xx >= T);
            if (bb2) {
                int l = __ffs(bb2) - 1;
                t_found = g * 32 + l;
                base_t  = running + __shfl_sync(FULL, xx, l)
                                  - __shfl_sync(FULL, v, l);
                break;
            }
            running += __shfl_sync(FULL, xx, 31);
        }

        if (t_found < 0) {
            token = min(sc * LCH + LCH, VV - 1);     // ulp-tie fallback
        } else {
            // level 3: 20 elements of thread t_found, same add order as pass
            long off0  = (long)sc * LCH + (long)t_found * PER_T;
            long obase = ((long)b * (KK + 1) + (allacc ? KK : r)) * VV + off0;
            long dbase = ((long)b * KK + r) * VV + off0;
            float val = 0.0f;
            if (lane < PER_T) {
                float o = op[obase + lane];
                val = allacc ? o : fmaxf(o - dp[dbase + lane], 0.0f);
            }
            float run = base_t;
            int found = PER_T;                       // fallback: end of span
#pragma unroll
            for (int i = 0; i < PER_T; ++i) {
                float v = __shfl_sync(FULL, val, i);
                run += v;
                if (found == PER_T && run >= T) found = i;
            }
            token = min((int)(off0 + found), VV - 1);
        }
    }

    if (lane == 0)
        out[b * (KK + 1) + na] = (float)token;
}

// ---------------------------------------------------------------------------
// Host launcher: classify inputs by element count (order-agnostic).
// ---------------------------------------------------------------------------
extern "C" void kernel_launch(void* const* d_in, const int* in_sizes, int n_in,
                              void* d_out, int out_size)
{
    const int*   dtok = nullptr;
    const float* dp   = nullptr;
    const float* op   = nullptr;
    const float* unif = nullptr;
    const float* su   = nullptr;

    int n512 = 0;
    for (int i = 0; i < n_in; ++i) {
        long sz = (long)in_sizes[i];
        if (sz == (long)BB * KK * VV)            dp = (const float*)d_in[i];
        else if (sz == (long)BB * (KK + 1) * VV) op = (const float*)d_in[i];
        else if (sz == BB)                       su = (const float*)d_in[i];
        else if (sz == BB * KK) {
            // relative order: draft_tokens, oracle_tokens, uniforms
            if      (n512 == 0) dtok = (const int*)d_in[i];
            else if (n512 == 2) unif = (const float*)d_in[i];
            ++n512;
        }
    }

    float* out = (float*)d_out;  // [tokens (B*(K+1)) | num_accepted (B)] as f32

    k_fused<<<BB * NS, TPB>>>(dtok, dp, op, unif, su, out);
}